// round 1
// baseline (speedup 1.0000x reference)
#include <cuda_runtime.h>

typedef unsigned long long ULL;

// ---------------- device scratch (allocation-free rule: __device__ globals) ---
__device__ float g_t1[256 * 16384];   // conv1 output (relu, masked): [256][128*128]
__device__ float g_t2[256 * 16384];   // conv2 output (relu, masked): [256][128*128]
__device__ int   g_count;             // number of active (group,patch) entries
__device__ int   g_list[256];         // compacted active entries: e = g*64 + py*8 + px

// ---------------- f32x2 helpers (sm_103a packed fp32, 2x FFMA throughput) -----
__device__ __forceinline__ ULL pack2(float lo, float hi) {
    ULL r; asm("mov.b64 %0, {%1,%2};" : "=l"(r) : "f"(lo), "f"(hi)); return r;
}
__device__ __forceinline__ void unpack2(ULL v, float& lo, float& hi) {
    asm("mov.b64 {%0,%1}, %2;" : "=f"(lo), "=f"(hi) : "l"(v));
}
__device__ __forceinline__ void ffma2(ULL& d, ULL a, ULL b) {
    asm("fma.rn.f32x2 %0, %1, %2, %0;" : "+l"(d) : "l"(a), "l"(b));
}

// ---------------- kernel 0: compact active (group,patch) list ----------------
__global__ void k_build(const float* __restrict__ mask) {
    int t = threadIdx.x;           // 0..255 : g*64 + py*8 + px
    if (t == 0) g_count = 0;
    __syncthreads();
    if (mask[t] > 0.5f) {
        int p = atomicAdd(&g_count, 1);
        g_list[p] = t;
    }
}

// ---------------- kernel 1: conv1 1x1 grouped 256->64, relu, masked ----------
// blocks 0..511   : compute (slot = bx>>1 into active list, half = bx&1 -> 32 outs)
// blocks 512..767 : zero-fill t1 for inactive (group,patch)
__global__ void __launch_bounds__(128) k_conv1(const float* __restrict__ x,
                                               const float* __restrict__ w1,
                                               const float* __restrict__ mask) {
    int t  = threadIdx.x;
    int bx = blockIdx.x;
    int pr = t >> 3, pc0 = (t & 7) << 1;   // thread owns pixel pair (row pr, cols pc0,pc0+1)

    if (bx >= 512) {
        int pg = bx - 512;
        if (mask[pg] > 0.5f) return;       // active handled by compute blocks
        int g = pg >> 6, cell = pg & 63;
        int py = cell >> 3, px = cell & 7;
        int pix = (py * 16 + pr) * 128 + px * 16 + pc0;
        float2 z = make_float2(0.f, 0.f);
        #pragma unroll 8
        for (int o = 0; o < 64; o++)
            *(float2*)&g_t1[(((g << 6) + o) << 14) + pix] = z;
        return;
    }

    int slot = bx >> 1, half = bx & 1;
    if (slot >= g_count) return;
    int e = g_list[slot];
    int g = e >> 6, cell = e & 63;
    int py = cell >> 3, px = cell & 7;
    int pix = (py * 16 + pr) * 128 + px * 16 + pc0;

    __shared__ ULL ws[64 * 34];            // [ii][o] duplicated {w,w}, pad 34 (16B-aligned pairs)
    ULL acc[32];
    #pragma unroll
    for (int o = 0; o < 32; o++) acc[o] = pack2(0.f, 0.f);

    int ocbase = (g << 6) + (half << 5);
    for (int k = 0; k < 4; k++) {          // K chunks of 64 input channels
        __syncthreads();
        #pragma unroll
        for (int rep = 0; rep < 16; rep++) {
            int idx = t + rep * 128;
            int o = idx >> 6, ii = idx & 63;
            float w = w1[(ocbase + o) * 256 + k * 64 + ii];
            ws[ii * 34 + o] = pack2(w, w);
        }
        __syncthreads();
        const float* xb = x + (((g << 8) + (k << 6)) << 14) + pix;
        #pragma unroll 4
        for (int ii = 0; ii < 64; ii++) {
            float2 xv = *(const float2*)(xb + (ii << 14));
            ULL xp = pack2(xv.x, xv.y);
            const ULL* wp = &ws[ii * 34];
            #pragma unroll
            for (int o = 0; o < 32; o++) ffma2(acc[o], xp, wp[o]);
        }
    }
    #pragma unroll
    for (int o = 0; o < 32; o++) {
        float lo, hi; unpack2(acc[o], lo, hi);
        *(float2*)&g_t1[((ocbase + o) << 14) + pix] =
            make_float2(fmaxf(lo, 0.f), fmaxf(hi, 0.f));
    }
}

// ---------------- kernel 2: conv2 3x3 grouped 64->64, relu, masked -----------
// grid 512: slot = bx>>1 active list, half = bx&1 (32 outputs). t2 written only for active.
__global__ void __launch_bounds__(128) k_conv2(const float* __restrict__ w2) {
    int t = threadIdx.x;
    int slot = blockIdx.x >> 1, half = blockIdx.x & 1;
    if (slot >= g_count) return;
    int e = g_list[slot];
    int g = e >> 6, cell = e & 63;
    int py = cell >> 3, px = cell & 7;
    int pr = t >> 3, pc0 = (t & 7) << 1;

    __shared__ float xs[8][324];           // [ci][r*18+c] 18x18 halo tile
    __shared__ ULL   ws[8 * 9 * 34];       // [(ci*9+tap)*34 + o] duplicated weights

    ULL acc[32];
    #pragma unroll
    for (int o = 0; o < 32; o++) acc[o] = pack2(0.f, 0.f);

    int ocbase = (g << 6) + (half << 5);
    int y0 = py * 16 - 1, x0 = px * 16 - 1;

    for (int cc = 0; cc < 8; cc++) {       // input-channel chunks of 8
        __syncthreads();
        for (int idx = t; idx < 8 * 324; idx += 128) {
            int ci = idx / 324, rem = idx - ci * 324;
            int r = rem / 18, c = rem - r * 18;
            int gy = y0 + r, gx = x0 + c;
            float v = 0.f;
            if ((unsigned)gy < 128u && (unsigned)gx < 128u)
                v = g_t1[(((g << 6) + (cc << 3) + ci) << 14) + gy * 128 + gx];
            xs[ci][rem] = v;
        }
        for (int idx = t; idx < 8 * 9 * 32; idx += 128) {
            int o = idx / 72, rem = idx - o * 72;   // rem = ci*9 + tap
            float w = w2[(ocbase + o) * 576 + cc * 72 + rem];
            ws[rem * 34 + o] = pack2(w, w);
        }
        __syncthreads();
        #pragma unroll 1
        for (int ci = 0; ci < 8; ci++) {
            #pragma unroll
            for (int r = 0; r < 3; r++) {
                const float* row = &xs[ci][(pr + r) * 18 + pc0];
                float v0 = row[0], v1 = row[1], v2 = row[2], v3 = row[3];
                ULL xp0 = pack2(v0, v1), xp1 = pack2(v1, v2), xp2 = pack2(v2, v3);
                const ULL* wp = &ws[(ci * 9 + r * 3) * 34];
                #pragma unroll
                for (int o = 0; o < 32; o++) ffma2(acc[o], xp0, wp[o]);
                #pragma unroll
                for (int o = 0; o < 32; o++) ffma2(acc[o], xp1, wp[34 + o]);
                #pragma unroll
                for (int o = 0; o < 32; o++) ffma2(acc[o], xp2, wp[68 + o]);
            }
        }
    }
    int pix = (py * 16 + pr) * 128 + px * 16 + pc0;
    #pragma unroll
    for (int o = 0; o < 32; o++) {
        float lo, hi; unpack2(acc[o], lo, hi);
        *(float2*)&g_t2[((ocbase + o) << 14) + pix] =
            make_float2(fmaxf(lo, 0.f), fmaxf(hi, 0.f));
    }
}

// ---------------- kernel 3: conv3 1x1 grouped 64->256 + residual + relu ------
// blocks 0..1023    : active compute (slot = bx>>2, q = bx&3 -> 64 outputs)
// blocks 1024..2047 : inactive copy out = relu(x)
__global__ void __launch_bounds__(128) k_conv3(const float* __restrict__ x,
                                               const float* __restrict__ w3,
                                               const float* __restrict__ mask,
                                               float* __restrict__ out) {
    int t  = threadIdx.x;
    int bx = blockIdx.x;
    int pr = t >> 3, pc0 = (t & 7) << 1;

    if (bx >= 1024) {
        int idx = bx - 1024;
        int pg = idx >> 2, q = idx & 3;
        if (mask[pg] > 0.5f) return;
        int g = pg >> 6, cell = pg & 63;
        int py = cell >> 3, px = cell & 7;
        int pix = (py * 16 + pr) * 128 + px * 16 + pc0;
        int cb = (g << 8) + (q << 6);
        #pragma unroll 8
        for (int o = 0; o < 64; o++) {
            float2 v = *(const float2*)&x[((cb + o) << 14) + pix];
            *(float2*)&out[((cb + o) << 14) + pix] =
                make_float2(fmaxf(v.x, 0.f), fmaxf(v.y, 0.f));
        }
        return;
    }

    int slot = bx >> 2, q = bx & 3;
    if (slot >= g_count) return;
    int e = g_list[slot];
    int g = e >> 6, cell = e & 63;
    int py = cell >> 3, px = cell & 7;
    int pix = (py * 16 + pr) * 128 + px * 16 + pc0;
    int cb = (g << 8) + (q << 6);

    __shared__ ULL ws[64 * 66];            // [j][o] duplicated, pad 66 (even -> 16B-aligned pairs)
    for (int idx = t; idx < 64 * 64; idx += 128) {
        int o = idx >> 6, j = idx & 63;
        float w = w3[((cb + o) << 6) + j];
        ws[j * 66 + o] = pack2(w, w);
    }
    __syncthreads();

    ULL acc[64];
    #pragma unroll
    for (int o = 0; o < 64; o++) acc[o] = pack2(0.f, 0.f);

    const float* t2b = g_t2 + ((g << 6) << 14) + pix;
    #pragma unroll 2
    for (int j = 0; j < 64; j++) {
        float2 xv = *(const float2*)(t2b + (j << 14));
        ULL xp = pack2(xv.x, xv.y);
        const ULL* wp = &ws[j * 66];
        #pragma unroll
        for (int o = 0; o < 64; o++) ffma2(acc[o], xp, wp[o]);
    }
    #pragma unroll 4
    for (int o = 0; o < 64; o++) {
        float lo, hi; unpack2(acc[o], lo, hi);
        float2 xr = *(const float2*)&x[((cb + o) << 14) + pix];
        *(float2*)&out[((cb + o) << 14) + pix] =
            make_float2(fmaxf(lo + xr.x, 0.f), fmaxf(hi + xr.y, 0.f));
    }
}

// ---------------- launch ------------------------------------------------------
extern "C" void kernel_launch(void* const* d_in, const int* in_sizes, int n_in,
                              void* d_out, int out_size) {
    const float* x    = (const float*)d_in[0];
    const float* mask = (const float*)d_in[1];
    const float* w1   = (const float*)d_in[2];
    const float* w2   = (const float*)d_in[3];
    const float* w3   = (const float*)d_in[4];
    float* out = (float*)d_out;

    k_build<<<1, 256>>>(mask);
    k_conv1<<<768, 128>>>(x, w1, mask);
    k_conv2<<<512, 128>>>(w2);
    k_conv3<<<2048, 128>>>(x, w3, mask, out);
}

// round 12
// speedup vs baseline: 1.5153x; 1.5153x over previous
#include <cuda_runtime.h>

typedef unsigned long long ULL;

// ---------------- device scratch -------------------------------------------
__device__ float g_t1[256 * 16384];      // conv1 out, dense [chan][128*128] (halo needed)
__device__ float g_t2p[256 * 64 * 256];  // conv2 out, patch-local [pg][chan 0..63][pix 0..255]
__device__ int   g_count;
__device__ int   g_list[256];            // active entries: e = g*64 + py*8 + px

// ---------------- f32x2 helpers --------------------------------------------
__device__ __forceinline__ ULL pack2(float lo, float hi) {
    ULL r; asm("mov.b64 %0, {%1,%2};" : "=l"(r) : "f"(lo), "f"(hi)); return r;
}
__device__ __forceinline__ void unpack2(ULL v, float& lo, float& hi) {
    asm("mov.b64 {%0,%1}, %2;" : "=f"(lo), "=f"(hi) : "l"(v));
}
__device__ __forceinline__ void ffma2(ULL& d, ULL a, ULL b) {
    asm("fma.rn.f32x2 %0, %1, %2, %0;" : "+l"(d) : "l"(a), "l"(b));
}
__device__ __forceinline__ ULL ldp(const float* p) {
    float2 v = *(const float2*)p; return pack2(v.x, v.y);
}

// ---------------- kernel 0: compact active list ----------------------------
__global__ void k_build(const float* __restrict__ mask) {
    int t = threadIdx.x;
    if (t == 0) g_count = 0;
    __syncthreads();
    if (mask[t] > 0.5f) {
        int p = atomicAdd(&g_count, 1);
        g_list[p] = t;
    }
}

// ---------------- kernel 1a: zero-fill t1 for inactive patches -------------
__global__ void __launch_bounds__(256) k_conv1z(const float* __restrict__ mask) {
    int pg = blockIdx.x;
    if (mask[pg] > 0.5f) return;
    int g = pg >> 6, cell = pg & 63;
    int py = cell >> 3, px = cell & 7;
    int t = threadIdx.x;
    int half = t >> 7;                      // 0/1: channels 0..31 / 32..63
    int tt = t & 127;
    int pr = tt >> 3, pc0 = (tt & 7) << 1;
    int pix = (py * 16 + pr) * 128 + px * 16 + pc0;
    float2 z = make_float2(0.f, 0.f);
    #pragma unroll 8
    for (int o = 0; o < 32; o++)
        *(float2*)&g_t1[(((g << 6) + (half << 5) + o) << 14) + pix] = z;
}

// ---------------- kernel 1b: conv1 1x1 grouped 256->64, relu, masked -------
// grid 512: slot=bx>>1 into active list, half=bx&1 -> 32 output channels
__global__ void __launch_bounds__(128) k_conv1(const float* __restrict__ x,
                                               const float* __restrict__ w1) {
    int t  = threadIdx.x;
    int pr = t >> 3, pc0 = (t & 7) << 1;

    int slot = blockIdx.x >> 1, half = blockIdx.x & 1;
    if (slot >= g_count) return;
    int e = g_list[slot];
    int g = e >> 6, cell = e & 63;
    int py = cell >> 3, px = cell & 7;
    int pix = (py * 16 + pr) * 128 + px * 16 + pc0;
    int ocbase = (g << 6) + (half << 5);

    __shared__ ULL ws[2][64 * 34];         // double-buffered duplicated weights

    #define STAGE1(kk, buf)                                                \
        {                                                                  \
            _Pragma("unroll")                                              \
            for (int rep = 0; rep < 16; rep++) {                           \
                int idx = t + rep * 128;                                   \
                int o = idx >> 6, ii = idx & 63;                           \
                float w = w1[(ocbase + o) * 256 + (kk) * 64 + ii];         \
                ws[buf][ii * 34 + o] = pack2(w, w);                        \
            }                                                              \
        }

    STAGE1(0, 0);
    __syncthreads();

    ULL acc[32];
    #pragma unroll
    for (int o = 0; o < 32; o++) acc[o] = pack2(0.f, 0.f);

    for (int k = 0; k < 4; k++) {
        int buf = k & 1;
        if (k < 3) STAGE1(k + 1, buf ^ 1);
        const float* xb = x + (((g << 8) + (k << 6)) << 14) + pix;
        ULL xv[2][4];
        #pragma unroll
        for (int u = 0; u < 4; u++) xv[0][u] = ldp(xb + (u << 14));
        #pragma unroll 2
        for (int ii0 = 0; ii0 < 64; ii0 += 4) {
            int pb = (ii0 >> 2) & 1;
            if (ii0 + 4 < 64) {
                #pragma unroll
                for (int u = 0; u < 4; u++)
                    xv[pb ^ 1][u] = ldp(xb + ((ii0 + 4 + u) << 14));
            }
            #pragma unroll
            for (int u = 0; u < 4; u++) {
                const ULL* wp = &ws[buf][(ii0 + u) * 34];
                #pragma unroll
                for (int o = 0; o < 32; o++) ffma2(acc[o], xv[pb][u], wp[o]);
            }
        }
        __syncthreads();
    }
    #pragma unroll
    for (int o = 0; o < 32; o++) {
        float lo, hi; unpack2(acc[o], lo, hi);
        *(float2*)&g_t1[((ocbase + o) << 14) + pix] =
            make_float2(fmaxf(lo, 0.f), fmaxf(hi, 0.f));
    }
    #undef STAGE1
}

// ---------------- kernel 2: conv2 3x3 grouped 64->64, relu, masked ---------
// grid 512: slot=bx>>1, half=bx&1 (32 outs). Writes patch-local t2p (active only).
__global__ void __launch_bounds__(128) k_conv2(const float* __restrict__ w2) {
    int t = threadIdx.x;
    int slot = blockIdx.x >> 1, half = blockIdx.x & 1;
    if (slot >= g_count) return;
    int e = g_list[slot];
    int g = e >> 6, cell = e & 63;
    int py = cell >> 3, px = cell & 7;
    int pr = t >> 3, pc0 = (t & 7) << 1;
    int ocbase = (g << 6) + (half << 5);
    int y0 = py * 16 - 1, x0 = px * 16 - 1;

    __shared__ float xs[2][4][324];        // double-buffered 18x18 halo tiles (4 chans)
    __shared__ ULL   wsd[2][4 * 9 * 34];   // double-buffered duplicated weights

    #define STAGE2(cc, buf)                                                 \
        {                                                                   \
            for (int idx = t; idx < 4 * 324; idx += 128) {                  \
                int ci = idx / 324, rem = idx - ci * 324;                   \
                int r = rem / 18, c2 = rem - r * 18;                        \
                int gy = y0 + r, gx = x0 + c2;                              \
                float v = 0.f;                                              \
                if ((unsigned)gy < 128u && (unsigned)gx < 128u)             \
                    v = g_t1[(((g << 6) + ((cc) << 2) + ci) << 14) +        \
                             gy * 128 + gx];                                \
                xs[buf][ci][rem] = v;                                       \
            }                                                               \
            for (int idx = t; idx < 4 * 9 * 32; idx += 128) {               \
                int o = idx / 36, rem = idx - o * 36;                       \
                float w = w2[(ocbase + o) * 576 + (cc) * 36 + rem];         \
                wsd[buf][rem * 34 + o] = pack2(w, w);                       \
            }                                                               \
        }

    STAGE2(0, 0);
    __syncthreads();

    ULL acc[32];
    #pragma unroll
    for (int o = 0; o < 32; o++) acc[o] = pack2(0.f, 0.f);

    for (int cc = 0; cc < 16; cc++) {
        int buf = cc & 1;
        if (cc < 15) STAGE2(cc + 1, buf ^ 1);
        #pragma unroll
        for (int ci = 0; ci < 4; ci++) {
            #pragma unroll
            for (int r = 0; r < 3; r++) {
                const float* row = &xs[buf][ci][(pr + r) * 18 + pc0];
                float v0 = row[0], v1 = row[1], v2 = row[2], v3 = row[3];
                ULL xp0 = pack2(v0, v1), xp1 = pack2(v1, v2), xp2 = pack2(v2, v3);
                const ULL* wp = &wsd[buf][(ci * 9 + r * 3) * 34];
                #pragma unroll
                for (int o = 0; o < 32; o++) ffma2(acc[o], xp0, wp[o]);
                #pragma unroll
                for (int o = 0; o < 32; o++) ffma2(acc[o], xp1, wp[34 + o]);
                #pragma unroll
                for (int o = 0; o < 32; o++) ffma2(acc[o], xp2, wp[68 + o]);
            }
        }
        __syncthreads();
    }

    int pix_local = pr * 16 + pc0;         // patch-local, contiguous per warp
    float* t2b = g_t2p + e * 16384 + pix_local;
    #pragma unroll
    for (int o = 0; o < 32; o++) {
        float lo, hi; unpack2(acc[o], lo, hi);
        *(float2*)&t2b[((half << 5) + o) * 256] =
            make_float2(fmaxf(lo, 0.f), fmaxf(hi, 0.f));
    }
    #undef STAGE2
}

// ---------------- kernel 3a: inactive patches out = relu(x) ----------------
__global__ void __launch_bounds__(256) k_conv3z(const float* __restrict__ x,
                                                const float* __restrict__ mask,
                                                float* __restrict__ out) {
    int pg = blockIdx.x >> 2, q = blockIdx.x & 3;
    if (mask[pg] > 0.5f) return;
    int g = pg >> 6, cell = pg & 63;
    int py = cell >> 3, px = cell & 7;
    int t = threadIdx.x;
    int half = t >> 7, tt = t & 127;
    int pr = tt >> 3, pc0 = (tt & 7) << 1;
    int pix = (py * 16 + pr) * 128 + px * 16 + pc0;
    int cb = (g << 8) + (q << 6) + (half << 5);
    #pragma unroll 8
    for (int o = 0; o < 32; o++) {
        float2 v = *(const float2*)&x[((cb + o) << 14) + pix];
        *(float2*)&out[((cb + o) << 14) + pix] =
            make_float2(fmaxf(v.x, 0.f), fmaxf(v.y, 0.f));
    }
}

// ---------------- kernel 3b: conv3 1x1 grouped 64->256 + residual + relu ---
// grid 2048: slot=bx>>3, q=bx&7 -> 32 output channels
__global__ void __launch_bounds__(128) k_conv3(const float* __restrict__ x,
                                               const float* __restrict__ w3,
                                               float* __restrict__ out) {
    int t  = threadIdx.x;
    int slot = blockIdx.x >> 3, q = blockIdx.x & 7;
    if (slot >= g_count) return;
    int e = g_list[slot];
    int g = e >> 6, cell = e & 63;
    int py = cell >> 3, px = cell & 7;
    int cb = (g << 8) + (q << 5);          // 32 output channels

    __shared__ ULL ws[64 * 34];
    #pragma unroll
    for (int rep = 0; rep < 16; rep++) {
        int idx = t + rep * 128;
        int j = idx & 63, o = idx >> 6;
        float w = w3[((cb + o) << 6) + j];
        ws[j * 34 + o] = pack2(w, w);
    }
    __syncthreads();

    ULL acc[32];
    #pragma unroll
    for (int o = 0; o < 32; o++) acc[o] = pack2(0.f, 0.f);

    const float* t2b = g_t2p + e * 16384 + (t << 1);   // warp: 256B contiguous
    ULL xv[2][4];
    #pragma unroll
    for (int u = 0; u < 4; u++) xv[0][u] = ldp(t2b + u * 256);
    #pragma unroll 2
    for (int j0 = 0; j0 < 64; j0 += 4) {
        int pb = (j0 >> 2) & 1;
        if (j0 + 4 < 64) {
            #pragma unroll
            for (int u = 0; u < 4; u++)
                xv[pb ^ 1][u] = ldp(t2b + (j0 + 4 + u) * 256);
        }
        #pragma unroll
        for (int u = 0; u < 4; u++) {
            const ULL* wp = &ws[(j0 + u) * 34];
            #pragma unroll
            for (int o = 0; o < 32; o++) ffma2(acc[o], xv[pb][u], wp[o]);
        }
    }

    int pix_local = t << 1;
    int r = pix_local >> 4, c = pix_local & 15;
    int gpix = (py * 16 + r) * 128 + px * 16 + c;
    #pragma unroll
    for (int o = 0; o < 32; o++) {
        float lo, hi; unpack2(acc[o], lo, hi);
        float2 xr = *(const float2*)&x[((cb + o) << 14) + gpix];
        *(float2*)&out[((cb + o) << 14) + gpix] =
            make_float2(fmaxf(lo + xr.x, 0.f), fmaxf(hi + xr.y, 0.f));
    }
}

// ---------------- launch ----------------------------------------------------
extern "C" void kernel_launch(void* const* d_in, const int* in_sizes, int n_in,
                              void* d_out, int out_size) {
    const float* x    = (const float*)d_in[0];
    const float* mask = (const float*)d_in[1];
    const float* w1   = (const float*)d_in[2];
    const float* w2   = (const float*)d_in[3];
    const float* w3   = (const float*)d_in[4];
    float* out = (float*)d_out;

    k_build<<<1, 256>>>(mask);
    k_conv1z<<<256, 256>>>(mask);
    k_conv1<<<512, 128>>>(x, w1);
    k_conv2<<<512, 128>>>(w2);
    k_conv3z<<<1024, 256>>>(x, mask, out);
    k_conv3<<<2048, 128>>>(x, w3, out);
}

// round 15
// speedup vs baseline: 1.5930x; 1.0513x over previous
#include <cuda_runtime.h>

typedef unsigned long long ULL;

// ---------------- device scratch -------------------------------------------
__device__ float g_t1[256 * 16384];      // conv1 out, dense [chan][128*128] (halo needed)
__device__ float g_t2p[256 * 64 * 256];  // conv2 out, patch-local [pg][chan 0..63][pix 0..255]
__device__ int   g_count;
__device__ int   g_list[256];            // active entries: e = g*64 + py*8 + px

// ---------------- f32x2 helpers --------------------------------------------
__device__ __forceinline__ ULL pack2(float lo, float hi) {
    ULL r; asm("mov.b64 %0, {%1,%2};" : "=l"(r) : "f"(lo), "f"(hi)); return r;
}
__device__ __forceinline__ void unpack2(ULL v, float& lo, float& hi) {
    asm("mov.b64 {%0,%1}, %2;" : "=f"(lo), "=f"(hi) : "l"(v));
}
__device__ __forceinline__ void ffma2(ULL& d, ULL a, ULL b) {
    asm("fma.rn.f32x2 %0, %1, %2, %0;" : "+l"(d) : "l"(a), "l"(b));
}
__device__ __forceinline__ ULL ldp(const float* p) {
    float2 v = *(const float2*)p; return pack2(v.x, v.y);
}

// ---------------- kernel 0: compact active list ----------------------------
__global__ void k_build(const float* __restrict__ mask) {
    int t = threadIdx.x;
    if (t == 0) g_count = 0;
    __syncthreads();
    if (mask[t] > 0.5f) {
        int p = atomicAdd(&g_count, 1);
        g_list[p] = t;
    }
}

// ---------------- kernel 1a: zero-fill t1 for inactive patches -------------
__global__ void __launch_bounds__(256) k_conv1z(const float* __restrict__ mask) {
    int pg = blockIdx.x;
    if (mask[pg] > 0.5f) return;
    int g = pg >> 6, cell = pg & 63;
    int py = cell >> 3, px = cell & 7;
    int t = threadIdx.x;
    int half = t >> 7;                      // 0/1: channels 0..31 / 32..63
    int tt = t & 127;
    int pr = tt >> 3, pc0 = (tt & 7) << 1;
    int pix = (py * 16 + pr) * 128 + px * 16 + pc0;
    float2 z = make_float2(0.f, 0.f);
    #pragma unroll 8
    for (int o = 0; o < 32; o++)
        *(float2*)&g_t1[(((g << 6) + (half << 5) + o) << 14) + pix] = z;
}

// ---------------- kernel 1b: conv1 1x1 grouped 256->64, relu, masked -------
// grid 512: slot=bx>>1 into active list, half=bx&1 -> 32 output channels
__global__ void __launch_bounds__(128) k_conv1(const float* __restrict__ x,
                                               const float* __restrict__ w1) {
    int t  = threadIdx.x;
    int pr = t >> 3, pc0 = (t & 7) << 1;

    int slot = blockIdx.x >> 1, half = blockIdx.x & 1;
    if (slot >= g_count) return;
    int e = g_list[slot];
    int g = e >> 6, cell = e & 63;
    int py = cell >> 3, px = cell & 7;
    int pix = (py * 16 + pr) * 128 + px * 16 + pc0;
    int ocbase = (g << 6) + (half << 5);

    __shared__ ULL ws[2][64 * 34];         // double-buffered duplicated weights

    #define STAGE1(kk, buf)                                                \
        {                                                                  \
            _Pragma("unroll")                                              \
            for (int rep = 0; rep < 16; rep++) {                           \
                int idx = t + rep * 128;                                   \
                int o = idx >> 6, ii = idx & 63;                           \
                float w = w1[(ocbase + o) * 256 + (kk) * 64 + ii];         \
                ws[buf][ii * 34 + o] = pack2(w, w);                        \
            }                                                              \
        }

    STAGE1(0, 0);
    __syncthreads();

    ULL acc[32];
    #pragma unroll
    for (int o = 0; o < 32; o++) acc[o] = pack2(0.f, 0.f);

    for (int k = 0; k < 4; k++) {
        int buf = k & 1;
        if (k < 3) STAGE1(k + 1, buf ^ 1);
        const float* xb = x + (((g << 8) + (k << 6)) << 14) + pix;
        ULL xv[2][4];
        #pragma unroll
        for (int u = 0; u < 4; u++) xv[0][u] = ldp(xb + (u << 14));
        #pragma unroll 2
        for (int ii0 = 0; ii0 < 64; ii0 += 4) {
            int pb = (ii0 >> 2) & 1;
            if (ii0 + 4 < 64) {
                #pragma unroll
                for (int u = 0; u < 4; u++)
                    xv[pb ^ 1][u] = ldp(xb + ((ii0 + 4 + u) << 14));
            }
            #pragma unroll
            for (int u = 0; u < 4; u++) {
                const ULL* wp = &ws[buf][(ii0 + u) * 34];
                #pragma unroll
                for (int o = 0; o < 32; o++) ffma2(acc[o], xv[pb][u], wp[o]);
            }
        }
        __syncthreads();
    }
    #pragma unroll
    for (int o = 0; o < 32; o++) {
        float lo, hi; unpack2(acc[o], lo, hi);
        *(float2*)&g_t1[((ocbase + o) << 14) + pix] =
            make_float2(fmaxf(lo, 0.f), fmaxf(hi, 0.f));
    }
    #undef STAGE1
}

// ---------------- kernel 2: conv2 3x3 grouped 64->64, relu, masked ---------
// grid 1024: slot=bx>>2, qtr=bx&3 -> 16 output channels per block.
// 4x more working blocks than R12 (occupancy was the binding constraint).
__global__ void __launch_bounds__(128) k_conv2(const float* __restrict__ w2) {
    int t = threadIdx.x;
    int slot = blockIdx.x >> 2, qtr = blockIdx.x & 3;
    if (slot >= g_count) return;
    int e = g_list[slot];
    int g = e >> 6, cell = e & 63;
    int py = cell >> 3, px = cell & 7;
    int pr = t >> 3, pc0 = (t & 7) << 1;
    int ocbase = (g << 6) + (qtr << 4);
    int y0 = py * 16 - 1, x0 = px * 16 - 1;

    __shared__ float xs[2][4][324];        // double-buffered 18x18 halo tiles (4 chans)
    __shared__ ULL   wsd[2][4 * 9 * 18];   // [(ci*9+tap)*18 + o], 16 outs, pad 18

    #define STAGE2(cc, buf)                                                 \
        {                                                                   \
            for (int idx = t; idx < 4 * 324; idx += 128) {                  \
                int ci = idx / 324, rem = idx - ci * 324;                   \
                int r = rem / 18, c2 = rem - r * 18;                        \
                int gy = y0 + r, gx = x0 + c2;                              \
                float v = 0.f;                                              \
                if ((unsigned)gy < 128u && (unsigned)gx < 128u)             \
                    v = g_t1[(((g << 6) + ((cc) << 2) + ci) << 14) +        \
                             gy * 128 + gx];                                \
                xs[buf][ci][rem] = v;                                       \
            }                                                               \
            for (int idx = t; idx < 4 * 9 * 16; idx += 128) {               \
                int o = idx / 36, rem = idx - o * 36;                       \
                float w = w2[(ocbase + o) * 576 + (cc) * 36 + rem];         \
                wsd[buf][rem * 18 + o] = pack2(w, w);                       \
            }                                                               \
        }

    STAGE2(0, 0);
    __syncthreads();

    ULL acc[16];
    #pragma unroll
    for (int o = 0; o < 16; o++) acc[o] = pack2(0.f, 0.f);

    for (int cc = 0; cc < 16; cc++) {
        int buf = cc & 1;
        if (cc < 15) STAGE2(cc + 1, buf ^ 1);
        #pragma unroll
        for (int ci = 0; ci < 4; ci++) {
            #pragma unroll
            for (int r = 0; r < 3; r++) {
                const float* row = &xs[buf][ci][(pr + r) * 18 + pc0];
                float v0 = row[0], v1 = row[1], v2 = row[2], v3 = row[3];
                ULL xp0 = pack2(v0, v1), xp1 = pack2(v1, v2), xp2 = pack2(v2, v3);
                const ULL* wp = &wsd[buf][(ci * 9 + r * 3) * 18];
                #pragma unroll
                for (int o = 0; o < 16; o++) ffma2(acc[o], xp0, wp[o]);
                #pragma unroll
                for (int o = 0; o < 16; o++) ffma2(acc[o], xp1, wp[18 + o]);
                #pragma unroll
                for (int o = 0; o < 16; o++) ffma2(acc[o], xp2, wp[36 + o]);
            }
        }
        __syncthreads();
    }

    int pix_local = pr * 16 + pc0;         // patch-local, contiguous per warp
    float* t2b = g_t2p + e * 16384 + pix_local;
    #pragma unroll
    for (int o = 0; o < 16; o++) {
        float lo, hi; unpack2(acc[o], lo, hi);
        *(float2*)&t2b[((qtr << 4) + o) * 256] =
            make_float2(fmaxf(lo, 0.f), fmaxf(hi, 0.f));
    }
    #undef STAGE2
}

// ---------------- kernel 3a: inactive patches out = relu(x) ----------------
__global__ void __launch_bounds__(256) k_conv3z(const float* __restrict__ x,
                                                const float* __restrict__ mask,
                                                float* __restrict__ out) {
    int pg = blockIdx.x >> 2, q = blockIdx.x & 3;
    if (mask[pg] > 0.5f) return;
    int g = pg >> 6, cell = pg & 63;
    int py = cell >> 3, px = cell & 7;
    int t = threadIdx.x;
    int half = t >> 7, tt = t & 127;
    int pr = tt >> 3, pc0 = (tt & 7) << 1;
    int pix = (py * 16 + pr) * 128 + px * 16 + pc0;
    int cb = (g << 8) + (q << 6) + (half << 5);
    #pragma unroll 8
    for (int o = 0; o < 32; o++) {
        float2 v = *(const float2*)&x[((cb + o) << 14) + pix];
        *(float2*)&out[((cb + o) << 14) + pix] =
            make_float2(fmaxf(v.x, 0.f), fmaxf(v.y, 0.f));
    }
}

// ---------------- kernel 3b: conv3 1x1 grouped 64->256 + residual + relu ---
// grid 2048: slot=bx>>3, q=bx&7 -> 32 output channels
__global__ void __launch_bounds__(128) k_conv3(const float* __restrict__ x,
                                               const float* __restrict__ w3,
                                               float* __restrict__ out) {
    int t  = threadIdx.x;
    int slot = blockIdx.x >> 3, q = blockIdx.x & 7;
    if (slot >= g_count) return;
    int e = g_list[slot];
    int g = e >> 6, cell = e & 63;
    int py = cell >> 3, px = cell & 7;
    int cb = (g << 8) + (q << 5);          // 32 output channels

    __shared__ ULL ws[64 * 34];
    #pragma unroll
    for (int rep = 0; rep < 16; rep++) {
        int idx = t + rep * 128;
        int j = idx & 63, o = idx >> 6;
        float w = w3[((cb + o) << 6) + j];
        ws[j * 34 + o] = pack2(w, w);
    }
    __syncthreads();

    ULL acc[32];
    #pragma unroll
    for (int o = 0; o < 32; o++) acc[o] = pack2(0.f, 0.f);

    const float* t2b = g_t2p + e * 16384 + (t << 1);   // warp: 256B contiguous
    ULL xv[2][4];
    #pragma unroll
    for (int u = 0; u < 4; u++) xv[0][u] = ldp(t2b + u * 256);
    #pragma unroll 2
    for (int j0 = 0; j0 < 64; j0 += 4) {
        int pb = (j0 >> 2) & 1;
        if (j0 + 4 < 64) {
            #pragma unroll
            for (int u = 0; u < 4; u++)
                xv[pb ^ 1][u] = ldp(t2b + (j0 + 4 + u) * 256);
        }
        #pragma unroll
        for (int u = 0; u < 4; u++) {
            const ULL* wp = &ws[(j0 + u) * 34];
            #pragma unroll
            for (int o = 0; o < 32; o++) ffma2(acc[o], xv[pb][u], wp[o]);
        }
    }

    int pix_local = t << 1;
    int r = pix_local >> 4, c = pix_local & 15;
    int gpix = (py * 16 + r) * 128 + px * 16 + c;
    #pragma unroll
    for (int o = 0; o < 32; o++) {
        float lo, hi; unpack2(acc[o], lo, hi);
        float2 xr = *(const float2*)&x[((cb + o) << 14) + gpix];
        *(float2*)&out[((cb + o) << 14) + gpix] =
            make_float2(fmaxf(lo + xr.x, 0.f), fmaxf(hi + xr.y, 0.f));
    }
}

// ---------------- launch ----------------------------------------------------
extern "C" void kernel_launch(void* const* d_in, const int* in_sizes, int n_in,
                              void* d_out, int out_size) {
    const float* x    = (const float*)d_in[0];
    const float* mask = (const float*)d_in[1];
    const float* w1   = (const float*)d_in[2];
    const float* w2   = (const float*)d_in[3];
    const float* w3   = (const float*)d_in[4];
    float* out = (float*)d_out;

    k_build<<<1, 256>>>(mask);
    k_conv1z<<<256, 256>>>(mask);
    k_conv1<<<512, 128>>>(x, w1);
    k_conv2<<<1024, 128>>>(w2);
    k_conv3z<<<1024, 256>>>(x, mask, out);
    k_conv3<<<2048, 128>>>(x, w3, out);
}

// round 16
// speedup vs baseline: 1.6427x; 1.0312x over previous
#include <cuda_runtime.h>

typedef unsigned long long ULL;

// ---------------- device scratch -------------------------------------------
__device__ float g_t1[256 * 16384];      // conv1 out, dense [chan][128*128] (halo needed)
__device__ float g_t2p[256 * 64 * 256];  // conv2 out, patch-local [pg][chan 0..63][pix 0..255]
__device__ int   g_count;
__device__ int   g_list[256];            // active entries: e = g*64 + py*8 + px

// ---------------- f32x2 helpers --------------------------------------------
__device__ __forceinline__ ULL pack2(float lo, float hi) {
    ULL r; asm("mov.b64 %0, {%1,%2};" : "=l"(r) : "f"(lo), "f"(hi)); return r;
}
__device__ __forceinline__ void unpack2(ULL v, float& lo, float& hi) {
    asm("mov.b64 {%0,%1}, %2;" : "=f"(lo), "=f"(hi) : "l"(v));
}
__device__ __forceinline__ void ffma2(ULL& d, ULL a, ULL b) {
    asm("fma.rn.f32x2 %0, %1, %2, %0;" : "+l"(d) : "l"(a), "l"(b));
}
__device__ __forceinline__ ULL ldp(const float* p) {
    float2 v = *(const float2*)p; return pack2(v.x, v.y);
}

// ---------------- kernel 0: compact active list ----------------------------
__global__ void k_build(const float* __restrict__ mask) {
    int t = threadIdx.x;
    if (t == 0) g_count = 0;
    __syncthreads();
    if (mask[t] > 0.5f) {
        int p = atomicAdd(&g_count, 1);
        g_list[p] = t;
    }
}

// ---------------- kernel 1a: zero-fill t1 for inactive patches -------------
__global__ void __launch_bounds__(256) k_conv1z(const float* __restrict__ mask) {
    int pg = blockIdx.x;
    if (mask[pg] > 0.5f) return;
    int g = pg >> 6, cell = pg & 63;
    int py = cell >> 3, px = cell & 7;
    int t = threadIdx.x;
    int half = t >> 7;                      // 0/1: channels 0..31 / 32..63
    int tt = t & 127;
    int pr = tt >> 3, pc0 = (tt & 7) << 1;
    int pix = (py * 16 + pr) * 128 + px * 16 + pc0;
    float2 z = make_float2(0.f, 0.f);
    #pragma unroll 8
    for (int o = 0; o < 32; o++)
        *(float2*)&g_t1[(((g << 6) + (half << 5) + o) << 14) + pix] = z;
}

// ---------------- kernel 1b: conv1 1x1 grouped 256->64, relu, masked -------
// grid 512: slot=bx>>1 into active list, half=bx&1 -> 32 output channels
__global__ void __launch_bounds__(128) k_conv1(const float* __restrict__ x,
                                               const float* __restrict__ w1) {
    int t  = threadIdx.x;
    int pr = t >> 3, pc0 = (t & 7) << 1;

    int slot = blockIdx.x >> 1, half = blockIdx.x & 1;
    if (slot >= g_count) return;
    int e = g_list[slot];
    int g = e >> 6, cell = e & 63;
    int py = cell >> 3, px = cell & 7;
    int pix = (py * 16 + pr) * 128 + px * 16 + pc0;
    int ocbase = (g << 6) + (half << 5);

    __shared__ ULL ws[2][64 * 34];         // double-buffered duplicated weights

    #define STAGE1(kk, buf)                                                \
        {                                                                  \
            _Pragma("unroll")                                              \
            for (int rep = 0; rep < 16; rep++) {                           \
                int idx = t + rep * 128;                                   \
                int o = idx >> 6, ii = idx & 63;                           \
                float w = w1[(ocbase + o) * 256 + (kk) * 64 + ii];         \
                ws[buf][ii * 34 + o] = pack2(w, w);                        \
            }                                                              \
        }

    STAGE1(0, 0);
    __syncthreads();

    ULL acc[32];
    #pragma unroll
    for (int o = 0; o < 32; o++) acc[o] = pack2(0.f, 0.f);

    for (int k = 0; k < 4; k++) {
        int buf = k & 1;
        if (k < 3) STAGE1(k + 1, buf ^ 1);
        const float* xb = x + (((g << 8) + (k << 6)) << 14) + pix;
        ULL xv[2][4];
        #pragma unroll
        for (int u = 0; u < 4; u++) xv[0][u] = ldp(xb + (u << 14));
        #pragma unroll 2
        for (int ii0 = 0; ii0 < 64; ii0 += 4) {
            int pb = (ii0 >> 2) & 1;
            if (ii0 + 4 < 64) {
                #pragma unroll
                for (int u = 0; u < 4; u++)
                    xv[pb ^ 1][u] = ldp(xb + ((ii0 + 4 + u) << 14));
            }
            #pragma unroll
            for (int u = 0; u < 4; u++) {
                const ULL* wp = &ws[buf][(ii0 + u) * 34];
                #pragma unroll
                for (int o = 0; o < 32; o++) ffma2(acc[o], xv[pb][u], wp[o]);
            }
        }
        __syncthreads();
    }
    #pragma unroll
    for (int o = 0; o < 32; o++) {
        float lo, hi; unpack2(acc[o], lo, hi);
        *(float2*)&g_t1[((ocbase + o) << 14) + pix] =
            make_float2(fmaxf(lo, 0.f), fmaxf(hi, 0.f));
    }
    #undef STAGE1
}

// ---------------- kernel 2: conv2 3x3 grouped 64->64, relu, masked ---------
// grid 2048: slot=bx>>3, oct=bx&7 -> 8 output channels per block.
// 8-way output split (occupancy still the binding constraint at R15's 22.4%),
// 8-channel input chunks (halves barrier count: 16 mainloop iters -> 8).
__global__ void __launch_bounds__(128) k_conv2(const float* __restrict__ w2) {
    int t = threadIdx.x;
    int slot = blockIdx.x >> 3, oct = blockIdx.x & 7;
    if (slot >= g_count) return;
    int e = g_list[slot];
    int g = e >> 6, cell = e & 63;
    int py = cell >> 3, px = cell & 7;
    int pr = t >> 3, pc0 = (t & 7) << 1;
    int ocbase = (g << 6) + (oct << 3);
    int y0 = py * 16 - 1, x0 = px * 16 - 1;

    __shared__ float xs[2][8][324];        // double-buffered 18x18 halo tiles (8 chans)
    __shared__ ULL   wsd[2][8 * 9 * 10];   // [(ci*9+tap)*10 + o], 8 outs, pad 10

    #define STAGE2(cc, buf)                                                 \
        {                                                                   \
            for (int idx = t; idx < 8 * 324; idx += 128) {                  \
                int ci = idx / 324, rem = idx - ci * 324;                   \
                int r = rem / 18, c2 = rem - r * 18;                        \
                int gy = y0 + r, gx = x0 + c2;                              \
                float v = 0.f;                                              \
                if ((unsigned)gy < 128u && (unsigned)gx < 128u)             \
                    v = g_t1[(((g << 6) + ((cc) << 3) + ci) << 14) +        \
                             gy * 128 + gx];                                \
                xs[buf][ci][rem] = v;                                       \
            }                                                               \
            for (int idx = t; idx < 8 * 9 * 8; idx += 128) {                \
                int o = idx / 72, rem = idx - o * 72;                       \
                float w = w2[(ocbase + o) * 576 + (cc) * 72 + rem];         \
                wsd[buf][rem * 10 + o] = pack2(w, w);                       \
            }                                                               \
        }

    STAGE2(0, 0);
    __syncthreads();

    ULL acc[8];
    #pragma unroll
    for (int o = 0; o < 8; o++) acc[o] = pack2(0.f, 0.f);

    for (int cc = 0; cc < 8; cc++) {
        int buf = cc & 1;
        if (cc < 7) STAGE2(cc + 1, buf ^ 1);
        #pragma unroll
        for (int ci = 0; ci < 8; ci++) {
            #pragma unroll
            for (int r = 0; r < 3; r++) {
                const float* row = &xs[buf][ci][(pr + r) * 18 + pc0];
                float v0 = row[0], v1 = row[1], v2 = row[2], v3 = row[3];
                ULL xp0 = pack2(v0, v1), xp1 = pack2(v1, v2), xp2 = pack2(v2, v3);
                const ULL* wp = &wsd[buf][(ci * 9 + r * 3) * 10];
                #pragma unroll
                for (int o = 0; o < 8; o++) ffma2(acc[o], xp0, wp[o]);
                #pragma unroll
                for (int o = 0; o < 8; o++) ffma2(acc[o], xp1, wp[10 + o]);
                #pragma unroll
                for (int o = 0; o < 8; o++) ffma2(acc[o], xp2, wp[20 + o]);
            }
        }
        __syncthreads();
    }

    int pix_local = pr * 16 + pc0;         // patch-local, contiguous per warp
    float* t2b = g_t2p + e * 16384 + pix_local;
    #pragma unroll
    for (int o = 0; o < 8; o++) {
        float lo, hi; unpack2(acc[o], lo, hi);
        *(float2*)&t2b[((oct << 3) + o) * 256] =
            make_float2(fmaxf(lo, 0.f), fmaxf(hi, 0.f));
    }
    #undef STAGE2
}

// ---------------- kernel 3a: inactive patches out = relu(x) ----------------
__global__ void __launch_bounds__(256) k_conv3z(const float* __restrict__ x,
                                                const float* __restrict__ mask,
                                                float* __restrict__ out) {
    int pg = blockIdx.x >> 2, q = blockIdx.x & 3;
    if (mask[pg] > 0.5f) return;
    int g = pg >> 6, cell = pg & 63;
    int py = cell >> 3, px = cell & 7;
    int t = threadIdx.x;
    int half = t >> 7, tt = t & 127;
    int pr = tt >> 3, pc0 = (tt & 7) << 1;
    int pix = (py * 16 + pr) * 128 + px * 16 + pc0;
    int cb = (g << 8) + (q << 6) + (half << 5);
    #pragma unroll 8
    for (int o = 0; o < 32; o++) {
        float2 v = *(const float2*)&x[((cb + o) << 14) + pix];
        *(float2*)&out[((cb + o) << 14) + pix] =
            make_float2(fmaxf(v.x, 0.f), fmaxf(v.y, 0.f));
    }
}

// ---------------- kernel 3b: conv3 1x1 grouped 64->256 + residual + relu ---
// grid 2048: slot=bx>>3, q=bx&7 -> 32 output channels
__global__ void __launch_bounds__(128) k_conv3(const float* __restrict__ x,
                                               const float* __restrict__ w3,
                                               float* __restrict__ out) {
    int t  = threadIdx.x;
    int slot = blockIdx.x >> 3, q = blockIdx.x & 7;
    if (slot >= g_count) return;
    int e = g_list[slot];
    int g = e >> 6, cell = e & 63;
    int py = cell >> 3, px = cell & 7;
    int cb = (g << 8) + (q << 5);          // 32 output channels

    __shared__ ULL ws[64 * 34];
    #pragma unroll
    for (int rep = 0; rep < 16; rep++) {
        int idx = t + rep * 128;
        int j = idx & 63, o = idx >> 6;
        float w = w3[((cb + o) << 6) + j];
        ws[j * 34 + o] = pack2(w, w);
    }
    __syncthreads();

    ULL acc[32];
    #pragma unroll
    for (int o = 0; o < 32; o++) acc[o] = pack2(0.f, 0.f);

    const float* t2b = g_t2p + e * 16384 + (t << 1);   // warp: 256B contiguous
    ULL xv[2][4];
    #pragma unroll
    for (int u = 0; u < 4; u++) xv[0][u] = ldp(t2b + u * 256);
    #pragma unroll 2
    for (int j0 = 0; j0 < 64; j0 += 4) {
        int pb = (j0 >> 2) & 1;
        if (j0 + 4 < 64) {
            #pragma unroll
            for (int u = 0; u < 4; u++)
                xv[pb ^ 1][u] = ldp(t2b + (j0 + 4 + u) * 256);
        }
        #pragma unroll
        for (int u = 0; u < 4; u++) {
            const ULL* wp = &ws[(j0 + u) * 34];
            #pragma unroll
            for (int o = 0; o < 32; o++) ffma2(acc[o], xv[pb][u], wp[o]);
        }
    }

    int pix_local = t << 1;
    int r = pix_local >> 4, c = pix_local & 15;
    int gpix = (py * 16 + r) * 128 + px * 16 + c;
    #pragma unroll
    for (int o = 0; o < 32; o++) {
        float lo, hi; unpack2(acc[o], lo, hi);
        float2 xr = *(const float2*)&x[((cb + o) << 14) + gpix];
        *(float2*)&out[((cb + o) << 14) + gpix] =
            make_float2(fmaxf(lo + xr.x, 0.f), fmaxf(hi + xr.y, 0.f));
    }
}

// ---------------- launch ----------------------------------------------------
extern "C" void kernel_launch(void* const* d_in, const int* in_sizes, int n_in,
                              void* d_out, int out_size) {
    const float* x    = (const float*)d_in[0];
    const float* mask = (const float*)d_in[1];
    const float* w1   = (const float*)d_in[2];
    const float* w2   = (const float*)d_in[3];
    const float* w3   = (const float*)d_in[4];
    float* out = (float*)d_out;

    k_build<<<1, 256>>>(mask);
    k_conv1z<<<256, 256>>>(mask);
    k_conv1<<<512, 128>>>(x, w1);
    k_conv2<<<2048, 128>>>(w2);
    k_conv3z<<<1024, 256>>>(x, mask, out);
    k_conv3<<<2048, 128>>>(x, w3, out);
}